// round 1
// baseline (speedup 1.0000x reference)
#include <cuda_runtime.h>
#include <cuda_fp16.h>
#include <cstdint>

// Fully-fused MLP: 64 -> 128 -> 128 -> 128 -> 128 -> 64, ReLU on all but last.
// fp16 tensor cores (mma.sync m16n8k16), fp32 accumulate, persistent CTAs,
// all weights + one in-place activation tile resident in shared memory.

#define NROWS        (1 << 20)
#define D_IN         64
#define D_HID        128
#define D_OUT        64
#define M_TILE       128
#define NTILES_TOTAL (NROWS / M_TILE)   // 8192
#define THREADS      256                // 8 warps: 4 (M) x 2 (N)

// shared-memory strides in halves (padded: conflict-free frag loads)
#define SA   136   // activations + 128-wide weights
#define SW0  72    // w_in (K = 64)

// half-element offsets within dynamic shared memory
#define OFF_ACT 0
#define OFF_W0  (128 * SA)                 // 17408
#define OFF_W1  (OFF_W0 + 128 * SW0)       // 26624
#define OFF_W2  (OFF_W1 + 128 * SA)        // 44032
#define OFF_W3  (OFF_W2 + 128 * SA)        // 61440
#define OFF_W4  (OFF_W3 + 128 * SA)        // 78848
#define HALVES_TOTAL (OFF_W4 + 64 * SA)    // 87552 halves
#define BIAS_BYTE_OFF (HALVES_TOTAL * 2)   // 175104 B (16B-aligned enough for float)
#define SMEM_BYTES   (BIAS_BYTE_OFF + (4 * 128 + 64) * 4)  // 177408 B

__device__ __forceinline__ void mma16816(float c[4], const uint32_t a[4], const uint32_t b[2]) {
    asm volatile(
        "mma.sync.aligned.m16n8k16.row.col.f32.f16.f16.f32 "
        "{%0,%1,%2,%3}, {%4,%5,%6,%7}, {%8,%9}, {%0,%1,%2,%3};\n"
        : "+f"(c[0]), "+f"(c[1]), "+f"(c[2]), "+f"(c[3])
        : "r"(a[0]), "r"(a[1]), "r"(a[2]), "r"(a[3]), "r"(b[0]), "r"(b[1]));
}

// Generic layer: out[m,n] = sum_k A[m,k] * W[n,k].
// Warp computes rows [wm*32, wm*32+32), cols [n0, n0 + NT*8).
template <int KDIM, int NT>
__device__ __forceinline__ void run_layer(
    const half* __restrict__ As, int sA,
    const half* __restrict__ Ws, int sW,
    int wm, int n0, int g, int t,
    float acc[2][8][4])
{
    const uint32_t* A32 = (const uint32_t*)As;
    const uint32_t* W32 = (const uint32_t*)Ws;
    const int m0 = wm * 32 + g;
#pragma unroll
    for (int ks = 0; ks < KDIM / 16; ks++) {
        const int k0 = ks * 16 + t * 2;
        uint32_t a[2][4];
#pragma unroll
        for (int mt = 0; mt < 2; mt++) {
            const int m = m0 + mt * 16;
            a[mt][0] = A32[(m * sA + k0) >> 1];
            a[mt][1] = A32[((m + 8) * sA + k0) >> 1];
            a[mt][2] = A32[(m * sA + k0 + 8) >> 1];
            a[mt][3] = A32[((m + 8) * sA + k0 + 8) >> 1];
        }
#pragma unroll
        for (int nt = 0; nt < NT; nt++) {
            const int n = n0 + nt * 8 + g;
            uint32_t b[2];
            b[0] = W32[(n * sW + k0) >> 1];
            b[1] = W32[(n * sW + k0 + 8) >> 1];
#pragma unroll
            for (int mt = 0; mt < 2; mt++) mma16816(acc[mt][nt], a[mt], b);
        }
    }
}

template <int NT>
__device__ __forceinline__ void epilogue_relu(
    const float acc[2][8][4], half* __restrict__ act,
    const float* __restrict__ bias, int wm, int n0, int g, int t)
{
#pragma unroll
    for (int mt = 0; mt < 2; mt++) {
        const int m = wm * 32 + mt * 16 + g;
#pragma unroll
        for (int nt = 0; nt < NT; nt++) {
            const int n = n0 + nt * 8 + t * 2;
            const float2 bb = *(const float2*)&bias[n];
            float v0 = fmaxf(acc[mt][nt][0] + bb.x, 0.f);
            float v1 = fmaxf(acc[mt][nt][1] + bb.y, 0.f);
            float v2 = fmaxf(acc[mt][nt][2] + bb.x, 0.f);
            float v3 = fmaxf(acc[mt][nt][3] + bb.y, 0.f);
            *(half2*)&act[m * SA + n]       = __floats2half2_rn(v0, v1);
            *(half2*)&act[(m + 8) * SA + n] = __floats2half2_rn(v2, v3);
        }
    }
}

__device__ __forceinline__ void zero_acc(float acc[2][8][4]) {
#pragma unroll
    for (int i = 0; i < 2; i++)
#pragma unroll
        for (int j = 0; j < 8; j++)
#pragma unroll
            for (int k = 0; k < 4; k++) acc[i][j][k] = 0.f;
}

__device__ __forceinline__ void load_x(const float* __restrict__ x, int tile, int tid,
                                       float4 xr[8]) {
    const float4* p = (const float4*)(x + (size_t)tile * (M_TILE * D_IN));
#pragma unroll
    for (int i = 0; i < 8; i++) xr[i] = p[tid + i * THREADS];
}

__global__ __launch_bounds__(THREADS, 1)
void FullyFusedMLP_kernel(
    const float* __restrict__ x,
    const float* __restrict__ w_in,  const float* __restrict__ b_in,
    const float* __restrict__ w_hid, const float* __restrict__ b_hid,
    const float* __restrict__ w_out, const float* __restrict__ b_out,
    float* __restrict__ out)
{
    extern __shared__ char smem_raw[];
    half* sh  = (half*)smem_raw;
    half* act = sh + OFF_ACT;
    half* w0  = sh + OFF_W0;
    half* w1  = sh + OFF_W1;
    half* w2  = sh + OFF_W2;
    half* w3  = sh + OFF_W3;
    half* w4  = sh + OFF_W4;
    float* bias = (float*)(smem_raw + BIAS_BYTE_OFF);
    // bias layout: [0:128) b_in, [128:512) b_hid (3x128), [512:576) b_out

    const int tid = threadIdx.x;

    // ---- load + convert all weights/biases into shared (once per CTA) ----
    for (int i = tid; i < 128 * 64; i += THREADS) {
        int n = i >> 6, k = i & 63;
        w0[n * SW0 + k] = __float2half(w_in[i]);
    }
    {
        half* wl[3] = {w1, w2, w3};
#pragma unroll
        for (int l = 0; l < 3; l++) {
            const float* src = w_hid + l * 128 * 128;
            half* dst = wl[l];
            for (int i = tid; i < 128 * 128; i += THREADS) {
                int n = i >> 7, k = i & 127;
                dst[n * SA + k] = __float2half(src[i]);
            }
        }
    }
    for (int i = tid; i < 64 * 128; i += THREADS) {
        int n = i >> 7, k = i & 127;
        w4[n * SA + k] = __float2half(w_out[i]);
    }
    for (int i = tid; i < 128; i += THREADS)     bias[i]       = b_in[i];
    for (int i = tid; i < 3 * 128; i += THREADS) bias[128 + i] = b_hid[i];
    for (int i = tid; i < 64; i += THREADS)      bias[512 + i] = b_out[i];
    // first __syncthreads inside the loop (after x STS) also fences the weights

    const int warp = tid >> 5, lane = tid & 31;
    const int wm = warp >> 1, wn = warp & 1;
    const int g = lane >> 2, t = lane & 3;

    float4 xr[8];
    int tile = blockIdx.x;
    if (tile < NTILES_TOTAL) load_x(x, tile, tid, xr);

    for (; tile < NTILES_TOTAL; tile += gridDim.x) {
        // stage x tile into activation buffer as fp16
#pragma unroll
        for (int i = 0; i < 8; i++) {
            const int j = tid + i * THREADS;     // float4 index 0..2047
            const int m = j >> 4;
            const int k = (j & 15) << 2;
            *(half2*)&act[m * SA + k]     = __floats2half2_rn(xr[i].x, xr[i].y);
            *(half2*)&act[m * SA + k + 2] = __floats2half2_rn(xr[i].z, xr[i].w);
        }
        __syncthreads();

        // prefetch next tile's x under the compute
        const int ntile = tile + gridDim.x;
        if (ntile < NTILES_TOTAL) load_x(x, ntile, tid, xr);

        float acc[2][8][4];

        // layer 0: 64 -> 128, ReLU
        zero_acc(acc);
        run_layer<64, 8>(act, SA, w0, SW0, wm, wn * 64, g, t, acc);
        __syncthreads();
        epilogue_relu<8>(acc, act, bias, wm, wn * 64, g, t);
        __syncthreads();

        // hidden layers 1..3: 128 -> 128, ReLU
        zero_acc(acc);
        run_layer<128, 8>(act, SA, w1, SA, wm, wn * 64, g, t, acc);
        __syncthreads();
        epilogue_relu<8>(acc, act, bias + 128, wm, wn * 64, g, t);
        __syncthreads();

        zero_acc(acc);
        run_layer<128, 8>(act, SA, w2, SA, wm, wn * 64, g, t, acc);
        __syncthreads();
        epilogue_relu<8>(acc, act, bias + 256, wm, wn * 64, g, t);
        __syncthreads();

        zero_acc(acc);
        run_layer<128, 8>(act, SA, w3, SA, wm, wn * 64, g, t, acc);
        __syncthreads();
        epilogue_relu<8>(acc, act, bias + 384, wm, wn * 64, g, t);
        __syncthreads();

        // layer 4: 128 -> 64, no activation, write fp32 to gmem
        zero_acc(acc);
        run_layer<128, 4>(act, SA, w4, SA, wm, wn * 32, g, t, acc);
        {
            const float* bo = bias + 512;
            const size_t base = (size_t)tile * M_TILE;
#pragma unroll
            for (int mt = 0; mt < 2; mt++) {
                const int m = wm * 32 + mt * 16 + g;
#pragma unroll
                for (int nt = 0; nt < 4; nt++) {
                    const int n = wn * 32 + nt * 8 + t * 2;
                    const float2 bb = *(const float2*)&bo[n];
                    float2 v0 = make_float2(acc[mt][nt][0] + bb.x, acc[mt][nt][1] + bb.y);
                    float2 v1 = make_float2(acc[mt][nt][2] + bb.x, acc[mt][nt][3] + bb.y);
                    *(float2*)&out[(base + m) * D_OUT + n]     = v0;
                    *(float2*)&out[(base + m + 8) * D_OUT + n] = v1;
                }
            }
        }
        __syncthreads();   // before next iteration overwrites act
    }
}

extern "C" void kernel_launch(void* const* d_in, const int* in_sizes, int n_in,
                              void* d_out, int out_size) {
    const float* x     = (const float*)d_in[0];
    const float* w_in  = (const float*)d_in[1];
    const float* b_in  = (const float*)d_in[2];
    const float* w_hid = (const float*)d_in[3];
    const float* b_hid = (const float*)d_in[4];
    const float* w_out = (const float*)d_in[5];
    const float* b_out = (const float*)d_in[6];
    float* out = (float*)d_out;

    int nsm = 148;
    cudaDeviceGetAttribute(&nsm, cudaDevAttrMultiProcessorCount, 0);
    if (nsm < 1) nsm = 148;
    int grid = nsm < NTILES_TOTAL ? nsm : NTILES_TOTAL;

    cudaFuncSetAttribute(FullyFusedMLP_kernel,
                         cudaFuncAttributeMaxDynamicSharedMemorySize, SMEM_BYTES);
    FullyFusedMLP_kernel<<<grid, THREADS, SMEM_BYTES>>>(
        x, w_in, b_in, w_hid, b_hid, w_out, b_out, out);
}

// round 2
// speedup vs baseline: 1.1346x; 1.1346x over previous
#include <cuda_runtime.h>
#include <cuda_fp16.h>
#include <cstdint>

// Fully-fused MLP 64->128->128->128->128->64, ReLU on all but last.
// Register-resident activations: each warp owns 32 rows end-to-end.
// C-fragment of layer L is re-packed in registers as A-fragment of layer L+1
// (no shared memory for activations, no __syncthreads in the main loop).
// Weights live in shared (padded, conflict-free); persistent CTAs.

#define NROWS      (1 << 20)
#define THREADS    256
#define WARPS      8
#define M_PER_WARP 32
#define M_TILE     (M_PER_WARP * WARPS)      // 256
#define NTILES     (NROWS / M_TILE)          // 4096

// shared strides in halves (row stride mod 32 words == 4 -> conflict-free B loads)
#define SA   136
#define SW0  72

#define OFF_W0  0
#define OFF_W1  (OFF_W0 + 128 * SW0)
#define OFF_W2  (OFF_W1 + 128 * SA)
#define OFF_W3  (OFF_W2 + 128 * SA)
#define OFF_W4  (OFF_W3 + 128 * SA)
#define HALVES  (OFF_W4 + 64 * SA)
#define BIAS_OFF (HALVES * 2)
#define SMEM_BYTES (BIAS_OFF + (4 * 128 + 64) * 4)

__device__ __forceinline__ void mma16816(float c[4], const uint32_t a[4], const uint32_t b[2]) {
    asm volatile(
        "mma.sync.aligned.m16n8k16.row.col.f32.f16.f16.f32 "
        "{%0,%1,%2,%3}, {%4,%5,%6,%7}, {%8,%9}, {%0,%1,%2,%3};\n"
        : "+f"(c[0]), "+f"(c[1]), "+f"(c[2]), "+f"(c[3])
        : "r"(a[0]), "r"(a[1]), "r"(a[2]), "r"(a[3]), "r"(b[0]), "r"(b[1]));
}

__device__ __forceinline__ uint32_t prelu2(float x, float y, float bx, float by) {
    half2 h = __floats2half2_rn(fmaxf(x + bx, 0.f), fmaxf(y + by, 0.f));
    return *(uint32_t*)&h;
}

__device__ __forceinline__ void zero16(float acc[2][16][4]) {
#pragma unroll
    for (int mt = 0; mt < 2; mt++)
#pragma unroll
        for (int j = 0; j < 16; j++)
#pragma unroll
            for (int r = 0; r < 4; r++) acc[mt][j][r] = 0.f;
}

// K=128 -> N=128 layer. a: A-frags (8 k-blocks), acc: C-frags (16 n-blocks).
__device__ __forceinline__ void layer128(const half* __restrict__ W,
                                         const uint32_t a[2][8][4],
                                         float acc[2][16][4], int g, int t) {
    const uint32_t* W32 = (const uint32_t*)W;
#pragma unroll
    for (int s = 0; s < 8; s++) {
        const int k0 = s * 16 + t * 2;
#pragma unroll
        for (int j = 0; j < 16; j++) {
            const int n = j * 8 + g;
            uint32_t b[2];
            b[0] = W32[(n * SA + k0) >> 1];
            b[1] = W32[(n * SA + k0 + 8) >> 1];
            mma16816(acc[0][j], a[0][s], b);
            mma16816(acc[1][j], a[1][s], b);
        }
    }
}

// C-frags (16 n-blocks, fp32) + bias + ReLU -> A-frags (8 k-blocks, fp16)
__device__ __forceinline__ void act_convert(const float acc[2][16][4],
                                            uint32_t a[2][8][4],
                                            const float* __restrict__ bias, int t) {
#pragma unroll
    for (int s = 0; s < 8; s++) {
        const float2 b0 = *(const float2*)&bias[s * 16 + t * 2];
        const float2 b1 = *(const float2*)&bias[s * 16 + 8 + t * 2];
#pragma unroll
        for (int mt = 0; mt < 2; mt++) {
            a[mt][s][0] = prelu2(acc[mt][2 * s][0],     acc[mt][2 * s][1],     b0.x, b0.y);
            a[mt][s][1] = prelu2(acc[mt][2 * s][2],     acc[mt][2 * s][3],     b0.x, b0.y);
            a[mt][s][2] = prelu2(acc[mt][2 * s + 1][0], acc[mt][2 * s + 1][1], b1.x, b1.y);
            a[mt][s][3] = prelu2(acc[mt][2 * s + 1][2], acc[mt][2 * s + 1][3], b1.x, b1.y);
        }
    }
}

__global__ __launch_bounds__(THREADS, 1)
void FullyFusedMLP_kernel(
    const float* __restrict__ x,
    const float* __restrict__ w_in,  const float* __restrict__ b_in,
    const float* __restrict__ w_hid, const float* __restrict__ b_hid,
    const float* __restrict__ w_out, const float* __restrict__ b_out,
    float* __restrict__ out)
{
    extern __shared__ char smem_raw[];
    half* sh = (half*)smem_raw;
    half* w0 = sh + OFF_W0;
    half* w1 = sh + OFF_W1;
    half* w2 = sh + OFF_W2;
    half* w3 = sh + OFF_W3;
    half* w4 = sh + OFF_W4;
    float* bias = (float*)(smem_raw + BIAS_OFF);
    // bias layout: [0:128) b_in, [128:512) b_hid (3x128), [512:576) b_out

    const int tid = threadIdx.x;

    // ---- stage weights/biases to shared once per CTA ----
    for (int i = tid; i < 128 * 64; i += THREADS) {
        int n = i >> 6, k = i & 63;
        w0[n * SW0 + k] = __float2half(w_in[i]);
    }
    {
        half* wl[3] = {w1, w2, w3};
#pragma unroll
        for (int l = 0; l < 3; l++) {
            const float* src = w_hid + l * 128 * 128;
            half* dst = wl[l];
            for (int i = tid; i < 128 * 128; i += THREADS) {
                int n = i >> 7, k = i & 127;
                dst[n * SA + k] = __float2half(src[i]);
            }
        }
    }
    for (int i = tid; i < 64 * 128; i += THREADS) {
        int n = i >> 7, k = i & 127;
        w4[n * SA + k] = __float2half(w_out[i]);
    }
    for (int i = tid; i < 128; i += THREADS)     bias[i]       = b_in[i];
    for (int i = tid; i < 3 * 128; i += THREADS) bias[128 + i] = b_hid[i];
    for (int i = tid; i < 64; i += THREADS)      bias[512 + i] = b_out[i];
    __syncthreads();   // the ONLY block-wide sync

    const int warp = tid >> 5, lane = tid & 31;
    const int g = lane >> 2, t = lane & 3;

    const uint32_t* w0_32 = (const uint32_t*)w0;
    const uint32_t* w4_32 = (const uint32_t*)w4;

    uint32_t a[2][8][4];     // A-frags / activations (registers)
    float acc[2][16][4];     // C-frags

    for (int tile = blockIdx.x; tile < NTILES; tile += gridDim.x) {
        const size_t row0 = (size_t)tile * M_TILE + warp * M_PER_WARP;

        // ---- load x tile (gmem -> A-frag registers, fp32 -> fp16) ----
        {
            const float* xp = x + row0 * 64;
#pragma unroll
            for (int mt = 0; mt < 2; mt++) {
                const int rA = mt * 16 + g;
#pragma unroll
                for (int s = 0; s < 4; s++) {
                    const int c0 = s * 16 + t * 2;
                    float2 v;
                    v = *(const float2*)&xp[rA * 64 + c0];
                    a[mt][s][0] = prelu2(v.x, v.y, 0.f, 0.f) ;  // no bias; relu(no-op for pack? NO
                    // x can be negative: must NOT relu. pack directly:
                    {
                        half2 h = __floats2half2_rn(v.x, v.y);
                        a[mt][s][0] = *(uint32_t*)&h;
                    }
                    v = *(const float2*)&xp[(rA + 8) * 64 + c0];
                    { half2 h = __floats2half2_rn(v.x, v.y); a[mt][s][1] = *(uint32_t*)&h; }
                    v = *(const float2*)&xp[rA * 64 + c0 + 8];
                    { half2 h = __floats2half2_rn(v.x, v.y); a[mt][s][2] = *(uint32_t*)&h; }
                    v = *(const float2*)&xp[(rA + 8) * 64 + c0 + 8];
                    { half2 h = __floats2half2_rn(v.x, v.y); a[mt][s][3] = *(uint32_t*)&h; }
                }
            }
        }

        // ---- layer 0: K=64 -> N=128 ----
        zero16(acc);
#pragma unroll
        for (int s = 0; s < 4; s++) {
            const int k0 = s * 16 + t * 2;
#pragma unroll
            for (int j = 0; j < 16; j++) {
                const int n = j * 8 + g;
                uint32_t b[2];
                b[0] = w0_32[(n * SW0 + k0) >> 1];
                b[1] = w0_32[(n * SW0 + k0 + 8) >> 1];
                mma16816(acc[0][j], a[0][s], b);
                mma16816(acc[1][j], a[1][s], b);
            }
        }
        act_convert(acc, a, bias, t);

        // ---- hidden layers 1..3: K=128 -> N=128 ----
        zero16(acc);
        layer128(w1, a, acc, g, t);
        act_convert(acc, a, bias + 128, t);

        zero16(acc);
        layer128(w2, a, acc, g, t);
        act_convert(acc, a, bias + 256, t);

        zero16(acc);
        layer128(w3, a, acc, g, t);
        act_convert(acc, a, bias + 384, t);

        // ---- layer 4: K=128 -> N=64, no activation, store fp32 ----
#pragma unroll
        for (int mt = 0; mt < 2; mt++)
#pragma unroll
            for (int j = 0; j < 8; j++)
#pragma unroll
                for (int r = 0; r < 4; r++) acc[mt][j][r] = 0.f;
#pragma unroll
        for (int s = 0; s < 8; s++) {
            const int k0 = s * 16 + t * 2;
#pragma unroll
            for (int j = 0; j < 8; j++) {
                const int n = j * 8 + g;
                uint32_t b[2];
                b[0] = w4_32[(n * SA + k0) >> 1];
                b[1] = w4_32[(n * SA + k0 + 8) >> 1];
                mma16816(acc[0][j], a[0][s], b);
                mma16816(acc[1][j], a[1][s], b);
            }
        }
        {
            const float* bo = bias + 512;
#pragma unroll
            for (int mt = 0; mt < 2; mt++) {
                const size_t r = row0 + mt * 16 + g;
#pragma unroll
                for (int j = 0; j < 8; j++) {
                    const int n = j * 8 + t * 2;
                    const float2 bb = *(const float2*)&bo[n];
                    float2 v0 = make_float2(acc[mt][j][0] + bb.x, acc[mt][j][1] + bb.y);
                    float2 v1 = make_float2(acc[mt][j][2] + bb.x, acc[mt][j][3] + bb.y);
                    *(float2*)&out[r * 64 + n]       = v0;
                    *(float2*)&out[(r + 8) * 64 + n] = v1;
                }
            }
        }
    }
}

extern "C" void kernel_launch(void* const* d_in, const int* in_sizes, int n_in,
                              void* d_out, int out_size) {
    const float* x     = (const float*)d_in[0];
    const float* w_in  = (const float*)d_in[1];
    const float* b_in  = (const float*)d_in[2];
    const float* w_hid = (const float*)d_in[3];
    const float* b_hid = (const float*)d_in[4];
    const float* w_out = (const float*)d_in[5];
    const float* b_out = (const float*)d_in[6];
    float* out = (float*)d_out;

    int nsm = 148;
    cudaDeviceGetAttribute(&nsm, cudaDevAttrMultiProcessorCount, 0);
    if (nsm < 1) nsm = 148;
    int grid = nsm < NTILES ? nsm : NTILES;

    cudaFuncSetAttribute(FullyFusedMLP_kernel,
                         cudaFuncAttributeMaxDynamicSharedMemorySize, SMEM_BYTES);
    FullyFusedMLP_kernel<<<grid, THREADS, SMEM_BYTES>>>(
        x, w_in, b_in, w_hid, b_hid, w_out, b_out, out);
}

// round 4
// speedup vs baseline: 1.1892x; 1.0481x over previous
#include <cuda_runtime.h>
#include <cuda_fp16.h>
#include <cstdint>

// Fully-fused MLP 64->128->128->128->128->64, ReLU on all but last (mma.sync).
// Register-resident activations (warp owns 32 rows end-to-end), weights in
// padded SMEM, bias preloaded into accumulator fragments, warp-local cp.async
// prefetch of the next tile's x. No __syncthreads in the main loop.

#define NROWS      (1 << 20)
#define THREADS    256
#define WARPS      8
#define M_PER_WARP 32
#define M_TILE     (M_PER_WARP * WARPS)      // 256
#define NTILES     (NROWS / M_TILE)          // 4096

// shared strides in halves (conflict-free B-frag loads)
#define SA   136
#define SW0  72

#define OFF_W0  0
#define OFF_W1  (OFF_W0 + 128 * SW0)
#define OFF_W2  (OFF_W1 + 128 * SA)
#define OFF_W3  (OFF_W2 + 128 * SA)
#define OFF_W4  (OFF_W3 + 128 * SA)
#define HALVES  (OFF_W4 + 64 * SA)               // 70144 halves
#define BIAS_OFF   (HALVES * 2)                  // 140288 B
#define STAGE_OFF  (BIAS_OFF + 576 * 4)          // 142592 B (16B aligned)
#define STAGE_F    68                            // padded floats per row
#define SMEM_BYTES (STAGE_OFF + M_TILE * STAGE_F * 4)   // 212224 B

__device__ __forceinline__ void mma16816(float c[4], const uint32_t a[4], const uint32_t b[2]) {
    asm volatile(
        "mma.sync.aligned.m16n8k16.row.col.f32.f16.f16.f32 "
        "{%0,%1,%2,%3}, {%4,%5,%6,%7}, {%8,%9}, {%0,%1,%2,%3};\n"
        : "+f"(c[0]), "+f"(c[1]), "+f"(c[2]), "+f"(c[3])
        : "r"(a[0]), "r"(a[1]), "r"(a[2]), "r"(a[3]), "r"(b[0]), "r"(b[1]));
}

__device__ __forceinline__ uint32_t smem_u32(const void* p) {
    uint32_t a;
    asm("{ .reg .u64 t; cvta.to.shared.u64 t, %1; cvt.u32.u64 %0, t; }" : "=r"(a) : "l"(p));
    return a;
}
#define CP_ASYNC16(dst, src) asm volatile("cp.async.cg.shared.global [%0], [%1], 16;" :: "r"(dst), "l"(src) : "memory")
#define CP_COMMIT()          asm volatile("cp.async.commit_group;" ::: "memory")
#define CP_WAIT0()           asm volatile("cp.async.wait_group 0;" ::: "memory")

__device__ __forceinline__ uint32_t packh2(float x, float y) {
    half2 h = __floats2half2_rn(x, y);
    return *(uint32_t*)&h;
}
__device__ __forceinline__ uint32_t relu_pack(float x, float y) {
    half2 h = __floats2half2_rn(fmaxf(x, 0.f), fmaxf(y, 0.f));
    return *(uint32_t*)&h;
}

// acc init = bias broadcast into C-frag layout (cols n = j*8 + t*2)
template <int NB>
__device__ __forceinline__ void init_acc_bias(float acc[2][16][4],
                                              const float* __restrict__ bias, int t) {
#pragma unroll
    for (int j = 0; j < NB; j++) {
        const float2 bb = *(const float2*)&bias[j * 8 + t * 2];
#pragma unroll
        for (int mt = 0; mt < 2; mt++) {
            acc[mt][j][0] = bb.x;
            acc[mt][j][1] = bb.y;
            acc[mt][j][2] = bb.x;
            acc[mt][j][3] = bb.y;
        }
    }
}

// K=128 -> N=128 layer: out[m,n] = acc + sum_k A[m,k]*W[n,k]
__device__ __forceinline__ void layer128(const half* __restrict__ W,
                                         const uint32_t a[2][8][4],
                                         float acc[2][16][4], int g, int t) {
    const uint32_t* W32 = (const uint32_t*)W;
#pragma unroll
    for (int s = 0; s < 8; s++) {
        const int k0 = s * 16 + t * 2;
#pragma unroll
        for (int j = 0; j < 16; j++) {
            const int n = j * 8 + g;
            uint32_t b[2];
            b[0] = W32[(n * SA + k0) >> 1];
            b[1] = W32[(n * SA + k0 + 8) >> 1];
            mma16816(acc[0][j], a[0][s], b);
            mma16816(acc[1][j], a[1][s], b);
        }
    }
}

// C-frags (bias already in) -> relu -> A-frags fp16
__device__ __forceinline__ void act_convert(const float acc[2][16][4],
                                            uint32_t a[2][8][4]) {
#pragma unroll
    for (int s = 0; s < 8; s++) {
#pragma unroll
        for (int mt = 0; mt < 2; mt++) {
            a[mt][s][0] = relu_pack(acc[mt][2 * s][0],     acc[mt][2 * s][1]);
            a[mt][s][1] = relu_pack(acc[mt][2 * s][2],     acc[mt][2 * s][3]);
            a[mt][s][2] = relu_pack(acc[mt][2 * s + 1][0], acc[mt][2 * s + 1][1]);
            a[mt][s][3] = relu_pack(acc[mt][2 * s + 1][2], acc[mt][2 * s + 1][3]);
        }
    }
}

// warp-local prefetch: 32 rows x 64 floats of x -> padded smem stage
__device__ __forceinline__ void prefetch_x(const float* __restrict__ xg,
                                           uint32_t stage_u32, int lane) {
#pragma unroll
    for (int i = 0; i < 16; i++) {
        const int id = i * 32 + lane;         // 0..511
        const int r = id >> 4, c4 = id & 15;
        CP_ASYNC16(stage_u32 + (uint32_t)(r * STAGE_F + c4 * 4) * 4u,
                   xg + r * 64 + c4 * 4);
    }
    CP_COMMIT();
}

__global__ __launch_bounds__(THREADS, 1)
void FullyFusedMLP_kernel(
    const float* __restrict__ x,
    const float* __restrict__ w_in,  const float* __restrict__ b_in,
    const float* __restrict__ w_hid, const float* __restrict__ b_hid,
    const float* __restrict__ w_out, const float* __restrict__ b_out,
    float* __restrict__ out)
{
    extern __shared__ char smem_raw[];
    half* sh = (half*)smem_raw;
    half* w0 = sh + OFF_W0;
    half* w1 = sh + OFF_W1;
    half* w2 = sh + OFF_W2;
    half* w3 = sh + OFF_W3;
    half* w4 = sh + OFF_W4;
    float* bias = (float*)(smem_raw + BIAS_OFF);
    // bias layout: [0:128) b_in, [128:512) b_hid (3x128), [512:576) b_out

    const int tid = threadIdx.x;

    // ---- stage weights/biases to shared once per CTA ----
    for (int i = tid; i < 128 * 64; i += THREADS) {
        int n = i >> 6, k = i & 63;
        w0[n * SW0 + k] = __float2half(w_in[i]);
    }
    {
        half* wl[3] = {w1, w2, w3};
#pragma unroll
        for (int l = 0; l < 3; l++) {
            const float* src = w_hid + l * 128 * 128;
            half* dst = wl[l];
            for (int i = tid; i < 128 * 128; i += THREADS) {
                int n = i >> 7, k = i & 127;
                dst[n * SA + k] = __float2half(src[i]);
            }
        }
    }
    for (int i = tid; i < 64 * 128; i += THREADS) {
        int n = i >> 7, k = i & 127;
        w4[n * SA + k] = __float2half(w_out[i]);
    }
    for (int i = tid; i < 128; i += THREADS)     bias[i]       = b_in[i];
    for (int i = tid; i < 3 * 128; i += THREADS) bias[128 + i] = b_hid[i];
    for (int i = tid; i < 64; i += THREADS)      bias[512 + i] = b_out[i];
    __syncthreads();   // the ONLY block-wide sync

    const int warp = tid >> 5, lane = tid & 31;
    const int g = lane >> 2, t = lane & 3;

    const uint32_t* w0_32 = (const uint32_t*)w0;
    const uint32_t* w4_32 = (const uint32_t*)w4;

    // warp-private x staging region (padded)
    float* stg = (float*)(smem_raw + STAGE_OFF) + warp * M_PER_WARP * STAGE_F;
    const uint32_t stg_u32 = smem_u32(stg);

    uint32_t a[2][8][4];     // A-frags / activations
    float acc[2][16][4];     // C-frags

    int tile = blockIdx.x;
    if (tile < NTILES)
        prefetch_x(x + ((size_t)tile * M_TILE + warp * M_PER_WARP) * 64, stg_u32, lane);

    for (; tile < NTILES; tile += gridDim.x) {
        const size_t row0 = (size_t)tile * M_TILE + warp * M_PER_WARP;

        // ---- consume staged x -> A-frags (fp32 -> fp16) ----
        CP_WAIT0();
        __syncwarp();
#pragma unroll
        for (int mt = 0; mt < 2; mt++) {
            const int rA = mt * 16 + g;
#pragma unroll
            for (int s = 0; s < 4; s++) {
                const int c0 = s * 16 + t * 2;
                float2 v0 = *(const float2*)&stg[rA * STAGE_F + c0];
                float2 v1 = *(const float2*)&stg[(rA + 8) * STAGE_F + c0];
                float2 v2 = *(const float2*)&stg[rA * STAGE_F + c0 + 8];
                float2 v3 = *(const float2*)&stg[(rA + 8) * STAGE_F + c0 + 8];
                a[mt][s][0] = packh2(v0.x, v0.y);
                a[mt][s][1] = packh2(v1.x, v1.y);
                a[mt][s][2] = packh2(v2.x, v2.y);
                a[mt][s][3] = packh2(v3.x, v3.y);
            }
        }
        __syncwarp();   // all lanes done reading before overwrite

        // ---- prefetch next tile's x under the compute ----
        const int ntile = tile + gridDim.x;
        if (ntile < NTILES)
            prefetch_x(x + ((size_t)ntile * M_TILE + warp * M_PER_WARP) * 64, stg_u32, lane);

        // ---- layer 0: K=64 -> N=128, ReLU ----
        init_acc_bias<16>(acc, bias, t);
#pragma unroll
        for (int s = 0; s < 4; s++) {
            const int k0 = s * 16 + t * 2;
#pragma unroll
            for (int j = 0; j < 16; j++) {
                const int n = j * 8 + g;
                uint32_t b[2];
                b[0] = w0_32[(n * SW0 + k0) >> 1];
                b[1] = w0_32[(n * SW0 + k0 + 8) >> 1];
                mma16816(acc[0][j], a[0][s], b);
                mma16816(acc[1][j], a[1][s], b);
            }
        }
        act_convert(acc, a);

        // ---- hidden layers 1..3 ----
        init_acc_bias<16>(acc, bias + 128, t);
        layer128(w1, a, acc, g, t);
        act_convert(acc, a);

        init_acc_bias<16>(acc, bias + 256, t);
        layer128(w2, a, acc, g, t);
        act_convert(acc, a);

        init_acc_bias<16>(acc, bias + 384, t);
        layer128(w3, a, acc, g, t);
        act_convert(acc, a);

        // ---- layer 4: K=128 -> N=64, no activation ----
        init_acc_bias<8>(acc, bias + 512, t);
#pragma unroll
        for (int s = 0; s < 8; s++) {
            const int k0 = s * 16 + t * 2;
#pragma unroll
            for (int j = 0; j < 8; j++) {
                const int n = j * 8 + g;
                uint32_t b[2];
                b[0] = w4_32[(n * SA + k0) >> 1];
                b[1] = w4_32[(n * SA + k0 + 8) >> 1];
                mma16816(acc[0][j], a[0][s], b);
                mma16816(acc[1][j], a[1][s], b);
            }
        }
        // store fp32 (bias already included)
#pragma unroll
        for (int mt = 0; mt < 2; mt++) {
            const size_t r = row0 + mt * 16 + g;
#pragma unroll
            for (int j = 0; j < 8; j++) {
                const int n = j * 8 + t * 2;
                *(float2*)&out[r * 64 + n]       = make_float2(acc[mt][j][0], acc[mt][j][1]);
                *(float2*)&out[(r + 8) * 64 + n] = make_float2(acc[mt][j][2], acc[mt][j][3]);
            }
        }
    }
}

extern "C" void kernel_launch(void* const* d_in, const int* in_sizes, int n_in,
                              void* d_out, int out_size) {
    const float* x     = (const float*)d_in[0];
    const float* w_in  = (const float*)d_in[1];
    const float* b_in  = (const float*)d_in[2];
    const float* w_hid = (const float*)d_in[3];
    const float* b_hid = (const float*)d_in[4];
    const float* w_out = (const float*)d_in[5];
    const float* b_out = (const float*)d_in[6];
    float* out = (float*)d_out;

    int nsm = 148;
    cudaDeviceGetAttribute(&nsm, cudaDevAttrMultiProcessorCount, 0);
    if (nsm < 1) nsm = 148;
    int grid = nsm < NTILES ? nsm : NTILES;

    cudaFuncSetAttribute(FullyFusedMLP_kernel,
                         cudaFuncAttributeMaxDynamicSharedMemorySize, SMEM_BYTES);
    FullyFusedMLP_kernel<<<grid, THREADS, SMEM_BYTES>>>(
        x, w_in, b_in, w_hid, b_hid, w_out, b_out, out);
}

// round 5
// speedup vs baseline: 1.1966x; 1.0062x over previous
#include <cuda_runtime.h>
#include <cuda_fp16.h>
#include <cstdint>

// Fully-fused MLP 64->128->128->128->128->64, ReLU on all but last (mma.sync).
// Register-resident activations (warp owns 32 rows end-to-end), weights in
// padded SMEM, bias preloaded into accumulator fragments, warp-local cp.async
// prefetch of the next tile's x. No __syncthreads in the main loop.

#define NROWS      (1 << 20)
#define THREADS    256
#define WARPS      8
#define M_PER_WARP 32
#define M_TILE     (M_PER_WARP * WARPS)      // 256
#define NTILES     (NROWS / M_TILE)          // 4096

// shared strides in halves (conflict-free B-frag loads)
#define SA   136
#define SW0  72

#define OFF_W0  0
#define OFF_W1  (OFF_W0 + 128 * SW0)
#define OFF_W2  (OFF_W1 + 128 * SA)
#define OFF_W3  (OFF_W2 + 128 * SA)
#define OFF_W4  (OFF_W3 + 128 * SA)
#define HALVES  (OFF_W4 + 64 * SA)               // 70144 halves
#define BIAS_OFF   (HALVES * 2)                  // 140288 B
#define STAGE_OFF  (BIAS_OFF + 576 * 4)          // 142592 B (16B aligned)
#define STAGE_F    68                            // padded floats per row
#define SMEM_BYTES (STAGE_OFF + M_TILE * STAGE_F * 4)   // 212224 B

__device__ __forceinline__ void mma16816(float c[4], const uint32_t a[4], const uint32_t b[2]) {
    asm volatile(
        "mma.sync.aligned.m16n8k16.row.col.f32.f16.f16.f32 "
        "{%0,%1,%2,%3}, {%4,%5,%6,%7}, {%8,%9}, {%0,%1,%2,%3};\n"
        : "+f"(c[0]), "+f"(c[1]), "+f"(c[2]), "+f"(c[3])
        : "r"(a[0]), "r"(a[1]), "r"(a[2]), "r"(a[3]), "r"(b[0]), "r"(b[1]));
}

__device__ __forceinline__ uint32_t smem_u32(const void* p) {
    uint32_t a;
    asm("{ .reg .u64 t; cvta.to.shared.u64 t, %1; cvt.u32.u64 %0, t; }" : "=r"(a) : "l"(p));
    return a;
}
#define CP_ASYNC16(dst, src) asm volatile("cp.async.cg.shared.global [%0], [%1], 16;" :: "r"(dst), "l"(src) : "memory")
#define CP_COMMIT()          asm volatile("cp.async.commit_group;" ::: "memory")
#define CP_WAIT0()           asm volatile("cp.async.wait_group 0;" ::: "memory")

__device__ __forceinline__ uint32_t packh2(float x, float y) {
    half2 h = __floats2half2_rn(x, y);
    return *(uint32_t*)&h;
}
__device__ __forceinline__ uint32_t relu_pack(float x, float y) {
    half2 h = __floats2half2_rn(fmaxf(x, 0.f), fmaxf(y, 0.f));
    return *(uint32_t*)&h;
}

// acc init = bias broadcast into C-frag layout (cols n = j*8 + t*2)
template <int NB>
__device__ __forceinline__ void init_acc_bias(float acc[2][16][4],
                                              const float* __restrict__ bias, int t) {
#pragma unroll
    for (int j = 0; j < NB; j++) {
        const float2 bb = *(const float2*)&bias[j * 8 + t * 2];
#pragma unroll
        for (int mt = 0; mt < 2; mt++) {
            acc[mt][j][0] = bb.x;
            acc[mt][j][1] = bb.y;
            acc[mt][j][2] = bb.x;
            acc[mt][j][3] = bb.y;
        }
    }
}

// K=128 -> N=128 layer: out[m,n] = acc + sum_k A[m,k]*W[n,k]
__device__ __forceinline__ void layer128(const half* __restrict__ W,
                                         const uint32_t a[2][8][4],
                                         float acc[2][16][4], int g, int t) {
    const uint32_t* W32 = (const uint32_t*)W;
#pragma unroll
    for (int s = 0; s < 8; s++) {
        const int k0 = s * 16 + t * 2;
#pragma unroll
        for (int j = 0; j < 16; j++) {
            const int n = j * 8 + g;
            uint32_t b[2];
            b[0] = W32[(n * SA + k0) >> 1];
            b[1] = W32[(n * SA + k0 + 8) >> 1];
            mma16816(acc[0][j], a[0][s], b);
            mma16816(acc[1][j], a[1][s], b);
        }
    }
}

// C-frags (bias already in) -> relu -> A-frags fp16
__device__ __forceinline__ void act_convert(const float acc[2][16][4],
                                            uint32_t a[2][8][4]) {
#pragma unroll
    for (int s = 0; s < 8; s++) {
#pragma unroll
        for (int mt = 0; mt < 2; mt++) {
            a[mt][s][0] = relu_pack(acc[mt][2 * s][0],     acc[mt][2 * s][1]);
            a[mt][s][1] = relu_pack(acc[mt][2 * s][2],     acc[mt][2 * s][3]);
            a[mt][s][2] = relu_pack(acc[mt][2 * s + 1][0], acc[mt][2 * s + 1][1]);
            a[mt][s][3] = relu_pack(acc[mt][2 * s + 1][2], acc[mt][2 * s + 1][3]);
        }
    }
}

// warp-local prefetch: 32 rows x 64 floats of x -> padded smem stage
__device__ __forceinline__ void prefetch_x(const float* __restrict__ xg,
                                           uint32_t stage_u32, int lane) {
#pragma unroll
    for (int i = 0; i < 16; i++) {
        const int id = i * 32 + lane;         // 0..511
        const int r = id >> 4, c4 = id & 15;
        CP_ASYNC16(stage_u32 + (uint32_t)(r * STAGE_F + c4 * 4) * 4u,
                   xg + r * 64 + c4 * 4);
    }
    CP_COMMIT();
}

__global__ __launch_bounds__(THREADS, 1)
void FullyFusedMLP_kernel(
    const float* __restrict__ x,
    const float* __restrict__ w_in,  const float* __restrict__ b_in,
    const float* __restrict__ w_hid, const float* __restrict__ b_hid,
    const float* __restrict__ w_out, const float* __restrict__ b_out,
    float* __restrict__ out)
{
    extern __shared__ char smem_raw[];
    half* sh = (half*)smem_raw;
    half* w0 = sh + OFF_W0;
    half* w1 = sh + OFF_W1;
    half* w2 = sh + OFF_W2;
    half* w3 = sh + OFF_W3;
    half* w4 = sh + OFF_W4;
    float* bias = (float*)(smem_raw + BIAS_OFF);
    // bias layout: [0:128) b_in, [128:512) b_hid (3x128), [512:576) b_out

    const int tid = threadIdx.x;

    // ---- stage weights/biases to shared once per CTA ----
    for (int i = tid; i < 128 * 64; i += THREADS) {
        int n = i >> 6, k = i & 63;
        w0[n * SW0 + k] = __float2half(w_in[i]);
    }
    {
        half* wl[3] = {w1, w2, w3};
#pragma unroll
        for (int l = 0; l < 3; l++) {
            const float* src = w_hid + l * 128 * 128;
            half* dst = wl[l];
            for (int i = tid; i < 128 * 128; i += THREADS) {
                int n = i >> 7, k = i & 127;
                dst[n * SA + k] = __float2half(src[i]);
            }
        }
    }
    for (int i = tid; i < 64 * 128; i += THREADS) {
        int n = i >> 7, k = i & 127;
        w4[n * SA + k] = __float2half(w_out[i]);
    }
    for (int i = tid; i < 128; i += THREADS)     bias[i]       = b_in[i];
    for (int i = tid; i < 3 * 128; i += THREADS) bias[128 + i] = b_hid[i];
    for (int i = tid; i < 64; i += THREADS)      bias[512 + i] = b_out[i];
    __syncthreads();   // the ONLY block-wide sync

    const int warp = tid >> 5, lane = tid & 31;
    const int g = lane >> 2, t = lane & 3;

    const uint32_t* w0_32 = (const uint32_t*)w0;
    const uint32_t* w4_32 = (const uint32_t*)w4;

    // warp-private x staging region (padded)
    float* stg = (float*)(smem_raw + STAGE_OFF) + warp * M_PER_WARP * STAGE_F;
    const uint32_t stg_u32 = smem_u32(stg);

    uint32_t a[2][8][4];     // A-frags / activations
    float acc[2][16][4];     // C-frags

    int tile = blockIdx.x;
    if (tile < NTILES)
        prefetch_x(x + ((size_t)tile * M_TILE + warp * M_PER_WARP) * 64, stg_u32, lane);

    for (; tile < NTILES; tile += gridDim.x) {
        const size_t row0 = (size_t)tile * M_TILE + warp * M_PER_WARP;

        // ---- consume staged x -> A-frags (fp32 -> fp16) ----
        CP_WAIT0();
        __syncwarp();
#pragma unroll
        for (int mt = 0; mt < 2; mt++) {
            const int rA = mt * 16 + g;
#pragma unroll
            for (int s = 0; s < 4; s++) {
                const int c0 = s * 16 + t * 2;
                float2 v0 = *(const float2*)&stg[rA * STAGE_F + c0];
                float2 v1 = *(const float2*)&stg[(rA + 8) * STAGE_F + c0];
                float2 v2 = *(const float2*)&stg[rA * STAGE_F + c0 + 8];
                float2 v3 = *(const float2*)&stg[(rA + 8) * STAGE_F + c0 + 8];
                a[mt][s][0] = packh2(v0.x, v0.y);
                a[mt][s][1] = packh2(v1.x, v1.y);
                a[mt][s][2] = packh2(v2.x, v2.y);
                a[mt][s][3] = packh2(v3.x, v3.y);
            }
        }
        __syncwarp();   // all lanes done reading before overwrite

        // ---- prefetch next tile's x under the compute ----
        const int ntile = tile + gridDim.x;
        if (ntile < NTILES)
            prefetch_x(x + ((size_t)ntile * M_TILE + warp * M_PER_WARP) * 64, stg_u32, lane);

        // ---- layer 0: K=64 -> N=128, ReLU ----
        init_acc_bias<16>(acc, bias, t);
#pragma unroll
        for (int s = 0; s < 4; s++) {
            const int k0 = s * 16 + t * 2;
#pragma unroll
            for (int j = 0; j < 16; j++) {
                const int n = j * 8 + g;
                uint32_t b[2];
                b[0] = w0_32[(n * SW0 + k0) >> 1];
                b[1] = w0_32[(n * SW0 + k0 + 8) >> 1];
                mma16816(acc[0][j], a[0][s], b);
                mma16816(acc[1][j], a[1][s], b);
            }
        }
        act_convert(acc, a);

        // ---- hidden layers 1..3 ----
        init_acc_bias<16>(acc, bias + 128, t);
        layer128(w1, a, acc, g, t);
        act_convert(acc, a);

        init_acc_bias<16>(acc, bias + 256, t);
        layer128(w2, a, acc, g, t);
        act_convert(acc, a);

        init_acc_bias<16>(acc, bias + 384, t);
        layer128(w3, a, acc, g, t);
        act_convert(acc, a);

        // ---- layer 4: K=128 -> N=64, no activation ----
        init_acc_bias<8>(acc, bias + 512, t);
#pragma unroll
        for (int s = 0; s < 8; s++) {
            const int k0 = s * 16 + t * 2;
#pragma unroll
            for (int j = 0; j < 8; j++) {
                const int n = j * 8 + g;
                uint32_t b[2];
                b[0] = w4_32[(n * SA + k0) >> 1];
                b[1] = w4_32[(n * SA + k0 + 8) >> 1];
                mma16816(acc[0][j], a[0][s], b);
                mma16816(acc[1][j], a[1][s], b);
            }
        }
        // store fp32 (bias already included)
#pragma unroll
        for (int mt = 0; mt < 2; mt++) {
            const size_t r = row0 + mt * 16 + g;
#pragma unroll
            for (int j = 0; j < 8; j++) {
                const int n = j * 8 + t * 2;
                *(float2*)&out[r * 64 + n]       = make_float2(acc[mt][j][0], acc[mt][j][1]);
                *(float2*)&out[(r + 8) * 64 + n] = make_float2(acc[mt][j][2], acc[mt][j][3]);
            }
        }
    }
}

extern "C" void kernel_launch(void* const* d_in, const int* in_sizes, int n_in,
                              void* d_out, int out_size) {
    const float* x     = (const float*)d_in[0];
    const float* w_in  = (const float*)d_in[1];
    const float* b_in  = (const float*)d_in[2];
    const float* w_hid = (const float*)d_in[3];
    const float* b_hid = (const float*)d_in[4];
    const float* w_out = (const float*)d_in[5];
    const float* b_out = (const float*)d_in[6];
    float* out = (float*)d_out;

    int nsm = 148;
    cudaDeviceGetAttribute(&nsm, cudaDevAttrMultiProcessorCount, 0);
    if (nsm < 1) nsm = 148;
    int grid = nsm < NTILES ? nsm : NTILES;

    cudaFuncSetAttribute(FullyFusedMLP_kernel,
                         cudaFuncAttributeMaxDynamicSharedMemorySize, SMEM_BYTES);
    FullyFusedMLP_kernel<<<grid, THREADS, SMEM_BYTES>>>(
        x, w_in, b_in, w_hid, b_hid, w_out, b_out, out);
}